// round 8
// baseline (speedup 1.0000x reference)
#include <cuda_runtime.h>
#include <math.h>

#define NF   24
#define FS   8
#define DY   32
#define DX   32
#define SEQL 300
#define TOTAL (NF*FS*DY*DX*SEQL)   // 58,982,400 floats
#define N4    (TOTAL/4)            // 14,745,600 float4
#define ROW4  (SEQL/4)             // 75

#define A_THREADS 256
#define A_ILP     4
#define A_BLOCKS  (N4 / (A_THREADS * A_ILP))   // 14400
// stride = 3,686,400 = 75 * 49152 -> idx%75 invariant over ILP slots

// Pass B: one warp per (f, yrow, xoff); each warp covers ALL 8 fs rows (MLP 8).
#define B_WARPS   (NF * 16 * 10)               // 3840
#define B_THREADS 256
#define B_BLOCKS  (B_WARPS / (B_THREADS / 32)) // 480
#define FS_STRIDE (DY * DX * SEQL)             // 307200 floats between fs slices

__device__ float g_max;   // reset to 0 via memset each replay (inputs >= 0)

// Hand-evaluated Python bbox math: left = int(32*l), w = int(32*round(l+0.3,4)) - left
__constant__ int c_left[NF] = {
    1, 2, 2, 3, 4, 5, 5, 6, 7, 7, 8, 9,
    9, 10, 11, 12, 12, 13, 14, 14, 15, 16, 16, 17
};
__constant__ int c_w[NF] = {
    10, 9, 10, 10, 9, 9, 10, 10, 9, 10, 10, 9,
    10, 10, 9, 9, 10, 10, 9, 10, 10, 9, 10, 10
};
__constant__ int c_edge_tok[6] = {2, 3, 9, 10, 11, 108};

// selected token: s==2 || s==3 || 9<=s<=108
__device__ __forceinline__ bool sel_tok(int s) {
    return ((unsigned)(s - 9) < 100u) || ((s & ~1) == 2);
}

// Pass A (unchanged, at HBM cap): out = in * (sel ? 0.918 : 1.0) + grid max.
__global__ void __launch_bounds__(A_THREADS)
apply_weaken_max(const float4* __restrict__ in, float4* __restrict__ out) {
    const int t      = blockIdx.x * A_THREADS + threadIdx.x;
    const int stride = A_BLOCKS * A_THREADS;

    const int s0 = (t % ROW4) * 4;
    float4 m;
    m.x = sel_tok(s0    ) ? 0.918f : 1.0f;
    m.y = sel_tok(s0 + 1) ? 0.918f : 1.0f;
    m.z = sel_tok(s0 + 2) ? 0.918f : 1.0f;
    m.w = sel_tok(s0 + 3) ? 0.918f : 1.0f;

    float4 v[A_ILP];
    #pragma unroll
    for (int k = 0; k < A_ILP; k++) v[k] = __ldcs(in + t + k * stride);

    float mx = 0.f;
    #pragma unroll
    for (int k = 0; k < A_ILP; k++) {
        float4 x = v[k];
        mx = fmaxf(mx, fmaxf(fmaxf(x.x, x.y), fmaxf(x.z, x.w)));
        __stcs(out + t + k * stride,
               make_float4(x.x * m.x, x.y * m.y, x.z * m.z, x.w * m.w));
    }

    #pragma unroll
    for (int off = 16; off; off >>= 1)
        mx = fmaxf(mx, __shfl_xor_sync(0xffffffffu, mx, off));
    __shared__ float sm[A_THREADS / 32];
    if ((threadIdx.x & 31) == 0) sm[threadIdx.x >> 5] = mx;
    __syncthreads();
    if (threadIdx.x < (A_THREADS / 32)) {
        mx = sm[threadIdx.x];
        #pragma unroll
        for (int off = (A_THREADS / 64); off; off >>= 1)
            mx = fmaxf(mx, __shfl_xor_sync(0xffffffffu, mx, off));
        if (threadIdx.x == 0)
            atomicMax((int*)&g_max, __float_as_int(mx));
    }
}

// Pass B: warp covers all 8 fs-rows of one spatial position; 8 independent
// 128-bit (or scalar) loads issued up front, then 8 stores. Streaming hints.
//   lane < 24 : float4 at tok 12+4*lane (16B-aligned: row*300 ≡ 0 mod 4)
//   lane 24-29: scalar edge tokens {2,3,9,10,11,108}
__global__ void __launch_bounds__(B_THREADS)
apply_strengthen(const float* __restrict__ in, float* __restrict__ out) {
    const int W    = (blockIdx.x * B_THREADS + threadIdx.x) >> 5;
    const int lane = threadIdx.x & 31;

    int pos = W;                           // [0, 3840)
    const int xoff = pos % 10;  pos /= 10;
    const int yrow = pos & 15;
    const int f    = pos >> 4;

    const int w = c_w[f];
    if (xoff >= w) return;                 // warp-uniform

    // normalized gaussian, fp32, one MUFU
    const float dx = (float)yrow * (16.0f / 15.0f) - 8.0f;
    float ax = ((8.0f / 15.0f) * (8.0f / 15.0f) - dx * dx) * (9.0f / 512.0f);
    float dy, dymin2, inv2sy2;
    if (w == 10) {
        dy = (float)xoff * (10.0f / 9.0f) - 5.0f;
        dymin2 = (5.0f / 9.0f) * (5.0f / 9.0f);
        inv2sy2 = 9.0f / 200.0f;
    } else {
        dy = (float)xoff * (9.0f / 8.0f) - 4.0f;
        dymin2 = 0.25f;
        inv2sy2 = 1.0f / 18.0f;
    }
    const float add = 0.125f * __expf(ax + (dymin2 - dy * dy) * inv2sy2) * g_max;

    // base element index at fs = 0
    const long base = (long)(f * FS * DY + 8 + yrow) * DX * SEQL
                    + (long)(c_left[f] + xoff) * SEQL;

    if (lane < 24) {
        const int tok = 12 + 4 * lane;
        float4 v[FS];
        #pragma unroll
        for (int r = 0; r < FS; r++)
            v[r] = __ldcs((const float4*)(in + base + (long)r * FS_STRIDE + tok));
        #pragma unroll
        for (int r = 0; r < FS; r++)
            __stcs((float4*)(out + base + (long)r * FS_STRIDE + tok),
                   make_float4(v[r].x + add, v[r].y + add,
                               v[r].z + add, v[r].w + add));
    } else if (lane < 30) {
        const int tok = c_edge_tok[lane - 24];
        float v[FS];
        #pragma unroll
        for (int r = 0; r < FS; r++)
            v[r] = __ldcs(in + base + (long)r * FS_STRIDE + tok);
        #pragma unroll
        for (int r = 0; r < FS; r++)
            __stcs(out + base + (long)r * FS_STRIDE + tok, v[r] + add);
    }
}

extern "C" void kernel_launch(void* const* d_in, const int* in_sizes, int n_in,
                              void* d_out, int out_size) {
    const float* in = (const float*)d_in[0];
    float* out = (float*)d_out;

    static void* gmax_addr = nullptr;
    if (!gmax_addr) cudaGetSymbolAddress(&gmax_addr, g_max);

    cudaMemsetAsync(gmax_addr, 0, sizeof(float));
    apply_weaken_max<<<A_BLOCKS, A_THREADS>>>((const float4*)in, (float4*)out);
    apply_strengthen<<<B_BLOCKS, B_THREADS>>>(in, out);
}